// round 8
// baseline (speedup 1.0000x reference)
#include <cuda_runtime.h>
#include <stdint.h>
#include <math.h>

#define NN   50000
#define EE   800000
#define INC  128
#define HID  96
#define OUTC 40

// ---- device scratch (static, no allocations) ----
__device__ float  g_h0 [NN * HID];
__device__ float  g_hqA[NN * HID];
__device__ float  g_hqB[NN * HID];
__device__ int    g_cnt[NN];
__device__ int    g_cur[NN];
__device__ int    g_rowptr[NN + 1];
__device__ int    g_col[EE];
__device__ float2 g_cw[EE];
__device__ float  g_dis[NN];
__device__ int    g_is64;

// ---- Threefry-2x32-20, JAX-exact ----
__device__ __forceinline__ void tf2x32(unsigned k0, unsigned k1,
                                       unsigned c0, unsigned c1,
                                       unsigned &o0, unsigned &o1)
{
    unsigned ks2 = k0 ^ k1 ^ 0x1BD11BDAu;
    unsigned x0 = c0 + k0, x1 = c1 + k1;
#define TFR(r) { x0 += x1; x1 = __funnelshift_l(x1, x1, r); x1 ^= x0; }
    TFR(13) TFR(15) TFR(26) TFR(6)
    x0 += k1;  x1 += ks2 + 1u;
    TFR(17) TFR(29) TFR(16) TFR(24)
    x0 += ks2; x1 += k0 + 2u;
    TFR(13) TFR(15) TFR(26) TFR(6)
    x0 += k0;  x1 += k1 + 3u;
    TFR(17) TFR(29) TFR(16) TFR(24)
    x0 += k1;  x1 += ks2 + 4u;
    TFR(13) TFR(15) TFR(26) TFR(6)
    x0 += ks2; x1 += k0 + 5u;
#undef TFR
    o0 = x0; o1 = x1;
}

// partitionable random_bits(32): counts=(0, idx), out = x0 ^ x1
__device__ __forceinline__ unsigned rbits(uint2 k, unsigned idx)
{
    unsigned a, b;
    tf2x32(k.x, k.y, 0u, idx, a, b);
    return a ^ b;
}

__device__ __forceinline__ float u01(unsigned bits)
{
    return __uint_as_float((bits >> 9) | 0x3f800000u) - 1.0f;
}

// XLA ErfInv32 (Giles)
__device__ __forceinline__ float erfinv_f(float x)
{
    float w = -log1pf(-x * x);
    float p;
    if (w < 5.0f) {
        w -= 2.5f;
        p = 2.81022636e-08f;
        p = fmaf(p, w, 3.43273939e-07f);
        p = fmaf(p, w, -3.5233877e-06f);
        p = fmaf(p, w, -4.39150654e-06f);
        p = fmaf(p, w, 0.00021858087f);
        p = fmaf(p, w, -0.00125372503f);
        p = fmaf(p, w, -0.00417768164f);
        p = fmaf(p, w, 0.246640727f);
        p = fmaf(p, w, 1.50140941f);
    } else {
        w = sqrtf(w) - 3.0f;
        p = -0.000200214257f;
        p = fmaf(p, w, 0.000100950558f);
        p = fmaf(p, w, 0.00134934322f);
        p = fmaf(p, w, -0.00367342844f);
        p = fmaf(p, w, 0.00573950773f);
        p = fmaf(p, w, -0.0076224613f);
        p = fmaf(p, w, 0.00943887047f);
        p = fmaf(p, w, 1.00167406f);
        p = fmaf(p, w, 2.83297682f);
    }
    return p * x;
}

// noise + relu + (dropout + next-layer dithered quantization)
__device__ __forceinline__ float epi(float z, unsigned idx,
                                     uint2 ke, uint2 kd, uint2 kqn,
                                     float dlt, float invd, int last)
{
    const float LO = -0.99999994f;
    float raw = u01(rbits(ke, idx));
    float u   = fmaxf(LO, fmaf(raw, 2.0f, LO));
    float g   = 1.4142135623730951f * erfinv_f(u);
    float h   = fmaxf(z + 0.01f * g, 0.0f);
    if (!last) {
        float ud = u01(rbits(kd, idx));
        h = (ud < 0.5f) ? (h + h) : 0.0f;
        float uq = u01(rbits(kqn, idx));
        float b  = (uq - 0.5f) * dlt;
        h = floorf((h + b) * invd) * dlt - b;
    }
    return h;
}

// ---- graph build ----
__global__ void k_zero()
{
    int i = blockIdx.x * blockDim.x + threadIdx.x;
    if (i < NN) { g_cnt[i] = 0; g_cur[i] = 0; }
}

__global__ void k_detect(const unsigned* __restrict__ w)
{
    if (threadIdx.x == 0) {
        int is64 = 1;
        for (int i = 0; i < 64; i++)
            if (w[2 * i + 1] != 0u) { is64 = 0; break; }
        g_is64 = is64;
    }
}

__global__ void k_count(const void* __restrict__ ei)
{
    int i = blockIdx.x * blockDim.x + threadIdx.x;
    if (i >= EE) return;
    int d = g_is64 ? (int)((const long long*)ei)[EE + i]
                   : ((const int*)ei)[EE + i];
    atomicAdd(&g_cnt[d], 1);
}

__global__ void k_scan()
{
    __shared__ int wsum[32];
    __shared__ int carry;
    int tid = threadIdx.x, lane = tid & 31, warp = tid >> 5;
    if (tid == 0) { carry = 0; g_rowptr[0] = 0; }
    __syncthreads();
    for (int base = 0; base < NN; base += 1024) {
        int i = base + tid;
        int s = (i < NN) ? g_cnt[i] : 0;
        #pragma unroll
        for (int o = 1; o < 32; o <<= 1) {
            int t = __shfl_up_sync(0xffffffffu, s, o);
            if (lane >= o) s += t;
        }
        if (lane == 31) wsum[warp] = s;
        __syncthreads();
        if (warp == 0) {
            int ws = wsum[lane];
            #pragma unroll
            for (int o = 1; o < 32; o <<= 1) {
                int t = __shfl_up_sync(0xffffffffu, ws, o);
                if (lane >= o) ws += t;
            }
            wsum[lane] = ws;
        }
        __syncthreads();
        int off = carry + ((warp > 0) ? wsum[warp - 1] : 0);
        if (i < NN) g_rowptr[i + 1] = off + s;
        __syncthreads();
        if (tid == 0) carry += wsum[31];
        __syncthreads();
    }
}

__global__ void k_dis()
{
    int i = blockIdx.x * blockDim.x + threadIdx.x;
    if (i < NN) g_dis[i] = (float)(1.0 / sqrt((double)(g_cnt[i] + 1)));
}

__global__ void k_fill(const void* __restrict__ ei)
{
    int i = blockIdx.x * blockDim.x + threadIdx.x;
    if (i >= EE) return;
    int s, d;
    if (g_is64) {
        s = (int)((const long long*)ei)[i];
        d = (int)((const long long*)ei)[EE + i];
    } else {
        s = ((const int*)ei)[i];
        d = ((const int*)ei)[EE + i];
    }
    int pos = g_rowptr[d] + atomicAdd(&g_cur[d], 1);
    g_col[pos] = s;
}

// canonicalize row order (bitwise-deterministic replays) + compute weights
__global__ void k_sortrow()
{
    int n = blockIdx.x * blockDim.x + threadIdx.x;
    if (n >= NN) return;
    int b = g_rowptr[n], e = g_rowptr[n + 1];
    for (int i = b + 1; i < e; i++) {
        int v = g_col[i], j = i - 1;
        while (j >= b && g_col[j] > v) { g_col[j + 1] = g_col[j]; j--; }
        g_col[j + 1] = v;
    }
    float dn = g_dis[n];
    for (int i = b; i < e; i++) {
        int s = g_col[i];
        g_cw[i] = make_float2(__int_as_float(s), g_dis[s] * dn);
    }
}

// ---- h0 = x @ Wp + b, plus layer-0 dithered quantization (delta = 1) ----
__global__ __launch_bounds__(384) void k_proj(const float* __restrict__ x,
                                              const float* __restrict__ Wp,
                                              const float* __restrict__ bp,
                                              uint2 kq0)
{
    __shared__ float sW[INC * HID];
    int tid = threadIdx.y * 96 + threadIdx.x;
    for (int i = tid; i < INC * HID; i += 384) sW[i] = Wp[i];
    __syncthreads();
    int c  = threadIdx.x;
    int r0 = blockIdx.x * 32;
    float acc[8];
    #pragma unroll
    for (int q = 0; q < 8; q++) acc[q] = 0.0f;
    #pragma unroll 4
    for (int kk = 0; kk < INC; kk++) {
        float wv = sW[kk * HID + c];
        #pragma unroll
        for (int q = 0; q < 8; q++) {
            int rr = r0 + threadIdx.y + q * 4;
            int rc = rr < NN ? rr : NN - 1;
            acc[q] = fmaf(x[(size_t)rc * INC + kk], wv, acc[q]);
        }
    }
    float bias = bp[c];
    #pragma unroll
    for (int q = 0; q < 8; q++) {
        int rr = r0 + threadIdx.y + q * 4;
        if (rr < NN) {
            float h = acc[q] + bias;
            unsigned idx = (unsigned)(rr * HID + c);
            g_h0[idx] = h;
            float b = u01(rbits(kq0, idx)) - 0.5f;
            g_hqA[idx] = floorf(h + b) - b;
        }
    }
}

// ---- fused GCN2 layer ----
#define WPB 8
__global__ __launch_bounds__(256) void k_layer(const float* __restrict__ Wk,
                                               uint2 ke, uint2 kd, uint2 kqn,
                                               float omb, float betaf,
                                               float dlt, float invd,
                                               int last, int dir)
{
    __shared__ float  sW[HID * HID];
    __shared__ float4 sT4[WPB][24];
    const float* __restrict__ hin  = dir ? g_hqB : g_hqA;
    float* __restrict__       hout = dir ? g_hqA : g_hqB;
    for (int i = threadIdx.x; i < HID * HID; i += 256) sW[i] = Wk[i];
    __syncthreads();
    int warp = threadIdx.x >> 5, lane = threadIdx.x & 31;
    for (int n = blockIdx.x * WPB + warp; n < NN; n += gridDim.x * WPB) {
        if (lane < 24) {
            float dn = g_dis[n];
            float ws = dn * dn;
            float4 v = ((const float4*)(hin + n * HID))[lane];
            float4 a = make_float4(v.x * ws, v.y * ws, v.z * ws, v.w * ws);
            int e1 = g_rowptr[n + 1];
            for (int e = g_rowptr[n]; e < e1; e++) {
                float2 cw = g_cw[e];
                const float4* rs = (const float4*)(hin + __float_as_int(cw.x) * HID);
                float4 u = rs[lane];
                float w = cw.y;
                a.x = fmaf(u.x, w, a.x); a.y = fmaf(u.y, w, a.y);
                a.z = fmaf(u.z, w, a.z); a.w = fmaf(u.w, w, a.w);
            }
            float4 h0v = ((const float4*)(g_h0 + n * HID))[lane];
            float4 t;
            t.x = 0.9f * a.x + 0.1f * h0v.x;
            t.y = 0.9f * a.y + 0.1f * h0v.y;
            t.z = 0.9f * a.z + 0.1f * h0v.z;
            t.w = 0.9f * a.w + 0.1f * h0v.w;
            sT4[warp][lane] = t;
        }
        __syncwarp();
        const float* sT = (const float*)sT4[warp];
        int f0 = lane, f1 = lane + 32, f2 = lane + 64;
        float t0 = sT[f0], t1 = sT[f1], t2 = sT[f2];
        float m0 = 0.0f, m1 = 0.0f, m2 = 0.0f;
        #pragma unroll 4
        for (int j = 0; j < HID; j++) {
            float tv = sT[j];
            m0 = fmaf(tv, sW[j * HID + f0], m0);
            m1 = fmaf(tv, sW[j * HID + f1], m1);
            m2 = fmaf(tv, sW[j * HID + f2], m2);
        }
        unsigned base = (unsigned)(n * HID);
        hout[base + f0] = epi(omb * t0 + betaf * m0, base + f0, ke, kd, kqn, dlt, invd, last);
        hout[base + f1] = epi(omb * t1 + betaf * m1, base + f1, ke, kd, kqn, dlt, invd, last);
        hout[base + f2] = epi(omb * t2 + betaf * m2, base + f2, ke, kd, kqn, dlt, invd, last);
        __syncwarp();
    }
}

// ---- out = concat(h0, h) @ Wo + bo ----
__global__ __launch_bounds__(256) void k_out(const float* __restrict__ Wo,
                                             const float* __restrict__ bo,
                                             float* __restrict__ out)
{
    __shared__ float sW[2 * HID * OUTC];
    __shared__ float sb[OUTC];
    for (int i = threadIdx.x; i < 2 * HID * OUTC; i += 256) sW[i] = Wo[i];
    for (int i = threadIdx.x; i < OUTC; i += 256) sb[i] = bo[i];
    __syncthreads();
    int warp = threadIdx.x >> 5, lane = threadIdx.x & 31;
    for (int n = blockIdx.x * 8 + warp; n < NN; n += gridDim.x * 8) {
        float a0 = 0.0f, a1 = 0.0f;
        const float* h0r = g_h0  + n * HID;
        const float* hfr = g_hqA + n * HID;   // layer 7 (dir=1) writes A
        #pragma unroll 4
        for (int j = 0; j < HID; j++) {
            float v = h0r[j];
            a0 = fmaf(v, sW[j * OUTC + lane], a0);
            if (lane < 8) a1 = fmaf(v, sW[j * OUTC + 32 + lane], a1);
        }
        #pragma unroll 4
        for (int j = 0; j < HID; j++) {
            float v = hfr[j];
            a0 = fmaf(v, sW[(HID + j) * OUTC + lane], a0);
            if (lane < 8) a1 = fmaf(v, sW[(HID + j) * OUTC + 32 + lane], a1);
        }
        out[n * OUTC + lane] = a0 + sb[lane];
        if (lane < 8) out[n * OUTC + 32 + lane] = a1 + sb[32 + lane];
    }
}

// ---- host threefry for key derivation ----
static void host_tf(unsigned k0, unsigned k1, unsigned c0, unsigned c1,
                    unsigned &o0, unsigned &o1)
{
    unsigned ks2 = k0 ^ k1 ^ 0x1BD11BDAu;
    unsigned x0 = c0 + k0, x1 = c1 + k1;
#define HR(r) { x0 += x1; x1 = (x1 << r) | (x1 >> (32 - r)); x1 ^= x0; }
    HR(13) HR(15) HR(26) HR(6)
    x0 += k1;  x1 += ks2 + 1u;
    HR(17) HR(29) HR(16) HR(24)
    x0 += ks2; x1 += k0 + 2u;
    HR(13) HR(15) HR(26) HR(6)
    x0 += k0;  x1 += k1 + 3u;
    HR(17) HR(29) HR(16) HR(24)
    x0 += k1;  x1 += ks2 + 4u;
    HR(13) HR(15) HR(26) HR(6)
    x0 += ks2; x1 += k0 + 5u;
#undef HR
    o0 = x0; o1 = x1;
}

extern "C" void kernel_launch(void* const* d_in, const int* in_sizes, int n_in,
                              void* d_out, int out_size)
{
    const float* x       = (const float*)d_in[0];
    const void*  ei      = d_in[1];
    const float* proj_w  = (const float*)d_in[2];
    const float* proj_b  = (const float*)d_in[3];
    const float* conv_ws = (const float*)d_in[4];
    const float* out_w   = (const float*)d_in[5];
    const float* out_b   = (const float*)d_in[6];
    float* out = (float*)d_out;

    // split chain from jax.random.key(42): kq,ke,kd,key = split(key,4)
    uint2 kq[8], ke[8], kd[8];
    unsigned K0 = 0u, K1 = 42u;
    for (int k = 0; k < 8; k++) {
        unsigned a, b;
        host_tf(K0, K1, 0u, 0u, a, b); kq[k] = make_uint2(a, b);
        host_tf(K0, K1, 0u, 1u, a, b); ke[k] = make_uint2(a, b);
        host_tf(K0, K1, 0u, 2u, a, b); kd[k] = make_uint2(a, b);
        host_tf(K0, K1, 0u, 3u, a, b); K0 = a; K1 = b;
    }

    k_zero  <<<196, 256>>>();
    k_detect<<<1, 32>>>((const unsigned*)ei);
    k_count <<<3125, 256>>>(ei);
    k_scan  <<<1, 1024>>>();
    k_dis   <<<196, 256>>>();
    k_fill  <<<3125, 256>>>(ei);
    k_sortrow<<<196, 256>>>();
    k_proj  <<<1563, dim3(96, 4)>>>(x, proj_w, proj_b, kq[0]);

    for (int k = 0; k < 8; k++) {
        double beta = log(0.5 / (double)(k + 1) + 1.0);
        int last = (k == 7);
        uint2 kqn = last ? make_uint2(0u, 0u) : kq[k + 1];
        float dlt  = (float)(1.0 / (double)(1u << (k + 1)));
        float invd = (float)(1u << (k + 1));
        k_layer<<<740, 256>>>(conv_ws + k * HID * HID, ke[k], kd[k], kqn,
                              (float)(1.0 - beta), (float)beta,
                              dlt, invd, last, k & 1);
    }
    k_out<<<392, 256>>>(out_w, out_b, out);
}

// round 9
// speedup vs baseline: 1.0699x; 1.0699x over previous
#include <cuda_runtime.h>
#include <stdint.h>
#include <math.h>

#define NN   50000
#define EE   800000
#define INC  128
#define HID  96
#define OUTC 40
#define NBLK 196   // ceil(NN/256)

// ---- device scratch (static, no allocations) ----
__device__ float  g_h0 [NN * HID];
__device__ float  g_hqA[NN * HID];
__device__ float  g_hqB[NN * HID];
__device__ int    g_cnt[NN];
__device__ int    g_cur[NN];
__device__ int    g_rowptr[NN + 1];
__device__ int    g_col[EE];
__device__ float2 g_cw[EE];
__device__ float  g_dis[NN];
__device__ int    g_bsum[NBLK];
__device__ int    g_boff[NBLK];
__device__ int    g_is64;

// ---- Threefry-2x32-20, JAX-exact ----
__device__ __forceinline__ void tf2x32(unsigned k0, unsigned k1,
                                       unsigned c0, unsigned c1,
                                       unsigned &o0, unsigned &o1)
{
    unsigned ks2 = k0 ^ k1 ^ 0x1BD11BDAu;
    unsigned x0 = c0 + k0, x1 = c1 + k1;
#define TFR(r) { x0 += x1; x1 = __funnelshift_l(x1, x1, r); x1 ^= x0; }
    TFR(13) TFR(15) TFR(26) TFR(6)
    x0 += k1;  x1 += ks2 + 1u;
    TFR(17) TFR(29) TFR(16) TFR(24)
    x0 += ks2; x1 += k0 + 2u;
    TFR(13) TFR(15) TFR(26) TFR(6)
    x0 += k0;  x1 += k1 + 3u;
    TFR(17) TFR(29) TFR(16) TFR(24)
    x0 += k1;  x1 += ks2 + 4u;
    TFR(13) TFR(15) TFR(26) TFR(6)
    x0 += ks2; x1 += k0 + 5u;
#undef TFR
    o0 = x0; o1 = x1;
}

// partitionable random_bits(32): counts=(0, idx), out = x0 ^ x1
__device__ __forceinline__ unsigned rbits(uint2 k, unsigned idx)
{
    unsigned a, b;
    tf2x32(k.x, k.y, 0u, idx, a, b);
    return a ^ b;
}

__device__ __forceinline__ float u01(unsigned bits)
{
    return __uint_as_float((bits >> 9) | 0x3f800000u) - 1.0f;
}

// XLA ErfInv32 (Giles); -log1p(-x*x) replaced by MUFU-based __logf.
// fma(-x,x,1) is single-rounded; min value ~1.2e-7 (u bounded away from +-1),
// so no cancellation blowup and no log(0).
__device__ __forceinline__ float erfinv_f(float x)
{
    float w = -__logf(fmaf(-x, x, 1.0f));
    float p;
    if (w < 5.0f) {
        w -= 2.5f;
        p = 2.81022636e-08f;
        p = fmaf(p, w, 3.43273939e-07f);
        p = fmaf(p, w, -3.5233877e-06f);
        p = fmaf(p, w, -4.39150654e-06f);
        p = fmaf(p, w, 0.00021858087f);
        p = fmaf(p, w, -0.00125372503f);
        p = fmaf(p, w, -0.00417768164f);
        p = fmaf(p, w, 0.246640727f);
        p = fmaf(p, w, 1.50140941f);
    } else {
        w = sqrtf(w) - 3.0f;
        p = -0.000200214257f;
        p = fmaf(p, w, 0.000100950558f);
        p = fmaf(p, w, 0.00134934322f);
        p = fmaf(p, w, -0.00367342844f);
        p = fmaf(p, w, 0.00573950773f);
        p = fmaf(p, w, -0.0076224613f);
        p = fmaf(p, w, 0.00943887047f);
        p = fmaf(p, w, 1.00167406f);
        p = fmaf(p, w, 2.83297682f);
    }
    return p * x;
}

// noise + relu + (dropout + next-layer dithered quantization)
__device__ __forceinline__ float epi(float z, unsigned idx,
                                     uint2 ke, uint2 kd, uint2 kqn,
                                     float dlt, float invd, int last)
{
    const float LO = -0.99999994f;
    float raw = u01(rbits(ke, idx));
    float u   = fmaxf(LO, fmaf(raw, 2.0f, LO));
    float g   = 1.4142135623730951f * erfinv_f(u);
    float h   = fmaxf(z + 0.01f * g, 0.0f);
    if (!last) {
        float ud = u01(rbits(kd, idx));
        h = (ud < 0.5f) ? (h + h) : 0.0f;
        float uq = u01(rbits(kqn, idx));
        float b  = (uq - 0.5f) * dlt;
        h = floorf((h + b) * invd) * dlt - b;
    }
    return h;
}

// ---- graph build ----
__global__ void k_zero()
{
    int i = blockIdx.x * blockDim.x + threadIdx.x;
    if (i < NN) { g_cnt[i] = 0; g_cur[i] = 0; }
}

__global__ void k_detect(const unsigned* __restrict__ w)
{
    if (threadIdx.x == 0) {
        int is64 = 1;
        for (int i = 0; i < 64; i++)
            if (w[2 * i + 1] != 0u) { is64 = 0; break; }
        g_is64 = is64;
    }
}

__global__ void k_count(const void* __restrict__ ei)
{
    int i = blockIdx.x * blockDim.x + threadIdx.x;
    if (i >= EE) return;
    int d = g_is64 ? (int)((const long long*)ei)[EE + i]
                   : ((const int*)ei)[EE + i];
    atomicAdd(&g_cnt[d], 1);
}

// hierarchical scan: per-block inclusive scan + block sums
__global__ void k_scan1()
{
    __shared__ int ws[8];
    int tid = threadIdx.x, lane = tid & 31, warp = tid >> 5;
    int i = blockIdx.x * 256 + tid;
    int v = (i < NN) ? g_cnt[i] : 0;
    int s = v;
    #pragma unroll
    for (int o = 1; o < 32; o <<= 1) {
        int t = __shfl_up_sync(0xffffffffu, s, o);
        if (lane >= o) s += t;
    }
    if (lane == 31) ws[warp] = s;
    __syncthreads();
    if (warp == 0) {
        int w = (lane < 8) ? ws[lane] : 0;
        #pragma unroll
        for (int o = 1; o < 8; o <<= 1) {
            int t = __shfl_up_sync(0xffffffffu, w, o);
            if (lane >= o) w += t;
        }
        if (lane < 8) ws[lane] = w;
    }
    __syncthreads();
    s += (warp > 0) ? ws[warp - 1] : 0;
    if (i < NN) g_rowptr[i + 1] = s;
    if (tid == 255) g_bsum[blockIdx.x] = s;
}

// scan of the 196 block sums -> exclusive offsets
__global__ void k_scan2()
{
    __shared__ int ws[8];
    int tid = threadIdx.x, lane = tid & 31, warp = tid >> 5;
    int v = (tid < NBLK) ? g_bsum[tid] : 0;
    int s = v;
    #pragma unroll
    for (int o = 1; o < 32; o <<= 1) {
        int t = __shfl_up_sync(0xffffffffu, s, o);
        if (lane >= o) s += t;
    }
    if (lane == 31) ws[warp] = s;
    __syncthreads();
    if (warp == 0) {
        int w = (lane < 8) ? ws[lane] : 0;
        #pragma unroll
        for (int o = 1; o < 8; o <<= 1) {
            int t = __shfl_up_sync(0xffffffffu, w, o);
            if (lane >= o) w += t;
        }
        if (lane < 8) ws[lane] = w;
    }
    __syncthreads();
    s += (warp > 0) ? ws[warp - 1] : 0;
    if (tid < NBLK) g_boff[tid] = s - v;     // exclusive
}

// add block offsets + compute degree rsqrt
__global__ void k_scan3()
{
    int i = blockIdx.x * blockDim.x + threadIdx.x;
    if (i < NN) {
        g_rowptr[i + 1] += g_boff[i >> 8];
        if (i == 0) g_rowptr[0] = 0;
        g_dis[i] = (float)(1.0 / sqrt((double)(g_cnt[i] + 1)));
    }
}

__global__ void k_fill(const void* __restrict__ ei)
{
    int i = blockIdx.x * blockDim.x + threadIdx.x;
    if (i >= EE) return;
    int s, d;
    if (g_is64) {
        s = (int)((const long long*)ei)[i];
        d = (int)((const long long*)ei)[EE + i];
    } else {
        s = ((const int*)ei)[i];
        d = ((const int*)ei)[EE + i];
    }
    int pos = g_rowptr[d] + atomicAdd(&g_cur[d], 1);
    g_col[pos] = s;
}

// canonicalize row order (bitwise-deterministic replays) + compute weights
__global__ void k_sortrow()
{
    int n = blockIdx.x * blockDim.x + threadIdx.x;
    if (n >= NN) return;
    int b = g_rowptr[n], e = g_rowptr[n + 1];
    for (int i = b + 1; i < e; i++) {
        int v = g_col[i], j = i - 1;
        while (j >= b && g_col[j] > v) { g_col[j + 1] = g_col[j]; j--; }
        g_col[j + 1] = v;
    }
    float dn = g_dis[n];
    for (int i = b; i < e; i++) {
        int s = g_col[i];
        g_cw[i] = make_float2(__int_as_float(s), g_dis[s] * dn);
    }
}

// ---- h0 = x @ Wp + b, plus layer-0 dithered quantization (delta = 1) ----
__global__ __launch_bounds__(384) void k_proj(const float* __restrict__ x,
                                              const float* __restrict__ Wp,
                                              const float* __restrict__ bp,
                                              uint2 kq0)
{
    __shared__ float sW[INC * HID];
    int tid = threadIdx.y * 96 + threadIdx.x;
    for (int i = tid; i < INC * HID; i += 384) sW[i] = Wp[i];
    __syncthreads();
    int c  = threadIdx.x;
    int r0 = blockIdx.x * 32;
    float acc[8];
    #pragma unroll
    for (int q = 0; q < 8; q++) acc[q] = 0.0f;
    #pragma unroll 4
    for (int kk = 0; kk < INC; kk++) {
        float wv = sW[kk * HID + c];
        #pragma unroll
        for (int q = 0; q < 8; q++) {
            int rr = r0 + threadIdx.y + q * 4;
            int rc = rr < NN ? rr : NN - 1;
            acc[q] = fmaf(x[(size_t)rc * INC + kk], wv, acc[q]);
        }
    }
    float bias = bp[c];
    #pragma unroll
    for (int q = 0; q < 8; q++) {
        int rr = r0 + threadIdx.y + q * 4;
        if (rr < NN) {
            float h = acc[q] + bias;
            unsigned idx = (unsigned)(rr * HID + c);
            g_h0[idx] = h;
            float b = u01(rbits(kq0, idx)) - 0.5f;
            g_hqA[idx] = floorf(h + b) - b;
        }
    }
}

// ---- fused GCN2 layer ----
#define WPB 8
__global__ __launch_bounds__(256) void k_layer(const float* __restrict__ Wk,
                                               uint2 ke, uint2 kd, uint2 kqn,
                                               float omb, float betaf,
                                               float dlt, float invd,
                                               int last, int dir)
{
    __shared__ float  sW[HID * HID];
    __shared__ float4 sT4[WPB][24];
    const float* __restrict__ hin  = dir ? g_hqB : g_hqA;
    float* __restrict__       hout = dir ? g_hqA : g_hqB;
    for (int i = threadIdx.x; i < HID * HID; i += 256) sW[i] = Wk[i];
    __syncthreads();
    int warp = threadIdx.x >> 5, lane = threadIdx.x & 31;
    for (int n = blockIdx.x * WPB + warp; n < NN; n += gridDim.x * WPB) {
        if (lane < 24) {
            float dn = g_dis[n];
            float ws = dn * dn;
            float4 v = ((const float4*)(hin + n * HID))[lane];
            float4 a = make_float4(v.x * ws, v.y * ws, v.z * ws, v.w * ws);
            int e  = g_rowptr[n];
            int e1 = g_rowptr[n + 1];
            // 2 edges in flight to cover L2 latency
            for (; e + 2 <= e1; e += 2) {
                float2 ca = g_cw[e];
                float2 cb = g_cw[e + 1];
                const float4* ra = (const float4*)(hin + __float_as_int(ca.x) * HID);
                const float4* rb = (const float4*)(hin + __float_as_int(cb.x) * HID);
                float4 ua = ra[lane];
                float4 ub = rb[lane];
                a.x = fmaf(ua.x, ca.y, a.x); a.y = fmaf(ua.y, ca.y, a.y);
                a.z = fmaf(ua.z, ca.y, a.z); a.w = fmaf(ua.w, ca.y, a.w);
                a.x = fmaf(ub.x, cb.y, a.x); a.y = fmaf(ub.y, cb.y, a.y);
                a.z = fmaf(ub.z, cb.y, a.z); a.w = fmaf(ub.w, cb.y, a.w);
            }
            if (e < e1) {
                float2 cw = g_cw[e];
                const float4* rs = (const float4*)(hin + __float_as_int(cw.x) * HID);
                float4 u = rs[lane];
                a.x = fmaf(u.x, cw.y, a.x); a.y = fmaf(u.y, cw.y, a.y);
                a.z = fmaf(u.z, cw.y, a.z); a.w = fmaf(u.w, cw.y, a.w);
            }
            float4 h0v = ((const float4*)(g_h0 + n * HID))[lane];
            float4 t;
            t.x = 0.9f * a.x + 0.1f * h0v.x;
            t.y = 0.9f * a.y + 0.1f * h0v.y;
            t.z = 0.9f * a.z + 0.1f * h0v.z;
            t.w = 0.9f * a.w + 0.1f * h0v.w;
            sT4[warp][lane] = t;
        }
        __syncwarp();
        const float* sT = (const float*)sT4[warp];
        int f0 = lane, f1 = lane + 32, f2 = lane + 64;
        float t0 = sT[f0], t1 = sT[f1], t2 = sT[f2];
        float m0 = 0.0f, m1 = 0.0f, m2 = 0.0f;
        #pragma unroll 4
        for (int j = 0; j < HID; j++) {
            float tv = sT[j];
            m0 = fmaf(tv, sW[j * HID + f0], m0);
            m1 = fmaf(tv, sW[j * HID + f1], m1);
            m2 = fmaf(tv, sW[j * HID + f2], m2);
        }
        unsigned base = (unsigned)(n * HID);
        hout[base + f0] = epi(omb * t0 + betaf * m0, base + f0, ke, kd, kqn, dlt, invd, last);
        hout[base + f1] = epi(omb * t1 + betaf * m1, base + f1, ke, kd, kqn, dlt, invd, last);
        hout[base + f2] = epi(omb * t2 + betaf * m2, base + f2, ke, kd, kqn, dlt, invd, last);
        __syncwarp();
    }
}

// ---- out = concat(h0, h) @ Wo + bo ----
__global__ __launch_bounds__(256) void k_out(const float* __restrict__ Wo,
                                             const float* __restrict__ bo,
                                             float* __restrict__ out)
{
    __shared__ float sW[2 * HID * OUTC];
    __shared__ float sb[OUTC];
    for (int i = threadIdx.x; i < 2 * HID * OUTC; i += 256) sW[i] = Wo[i];
    for (int i = threadIdx.x; i < OUTC; i += 256) sb[i] = bo[i];
    __syncthreads();
    int warp = threadIdx.x >> 5, lane = threadIdx.x & 31;
    for (int n = blockIdx.x * 8 + warp; n < NN; n += gridDim.x * 8) {
        float a0 = 0.0f, a1 = 0.0f;
        const float* h0r = g_h0  + n * HID;
        const float* hfr = g_hqA + n * HID;   // layer 7 (dir=1) writes A
        #pragma unroll 4
        for (int j = 0; j < HID; j++) {
            float v = h0r[j];
            a0 = fmaf(v, sW[j * OUTC + lane], a0);
            if (lane < 8) a1 = fmaf(v, sW[j * OUTC + 32 + lane], a1);
        }
        #pragma unroll 4
        for (int j = 0; j < HID; j++) {
            float v = hfr[j];
            a0 = fmaf(v, sW[(HID + j) * OUTC + lane], a0);
            if (lane < 8) a1 = fmaf(v, sW[(HID + j) * OUTC + 32 + lane], a1);
        }
        out[n * OUTC + lane] = a0 + sb[lane];
        if (lane < 8) out[n * OUTC + 32 + lane] = a1 + sb[32 + lane];
    }
}

// ---- host threefry for key derivation ----
static void host_tf(unsigned k0, unsigned k1, unsigned c0, unsigned c1,
                    unsigned &o0, unsigned &o1)
{
    unsigned ks2 = k0 ^ k1 ^ 0x1BD11BDAu;
    unsigned x0 = c0 + k0, x1 = c1 + k1;
#define HR(r) { x0 += x1; x1 = (x1 << r) | (x1 >> (32 - r)); x1 ^= x0; }
    HR(13) HR(15) HR(26) HR(6)
    x0 += k1;  x1 += ks2 + 1u;
    HR(17) HR(29) HR(16) HR(24)
    x0 += ks2; x1 += k0 + 2u;
    HR(13) HR(15) HR(26) HR(6)
    x0 += k0;  x1 += k1 + 3u;
    HR(17) HR(29) HR(16) HR(24)
    x0 += k1;  x1 += ks2 + 4u;
    HR(13) HR(15) HR(26) HR(6)
    x0 += ks2; x1 += k0 + 5u;
#undef HR
    o0 = x0; o1 = x1;
}

extern "C" void kernel_launch(void* const* d_in, const int* in_sizes, int n_in,
                              void* d_out, int out_size)
{
    const float* x       = (const float*)d_in[0];
    const void*  ei      = d_in[1];
    const float* proj_w  = (const float*)d_in[2];
    const float* proj_b  = (const float*)d_in[3];
    const float* conv_ws = (const float*)d_in[4];
    const float* out_w   = (const float*)d_in[5];
    const float* out_b   = (const float*)d_in[6];
    float* out = (float*)d_out;

    // split chain from jax.random.key(42): kq,ke,kd,key = split(key,4)
    uint2 kq[8], ke[8], kd[8];
    unsigned K0 = 0u, K1 = 42u;
    for (int k = 0; k < 8; k++) {
        unsigned a, b;
        host_tf(K0, K1, 0u, 0u, a, b); kq[k] = make_uint2(a, b);
        host_tf(K0, K1, 0u, 1u, a, b); ke[k] = make_uint2(a, b);
        host_tf(K0, K1, 0u, 2u, a, b); kd[k] = make_uint2(a, b);
        host_tf(K0, K1, 0u, 3u, a, b); K0 = a; K1 = b;
    }

    k_zero   <<<NBLK, 256>>>();
    k_detect <<<1, 32>>>((const unsigned*)ei);
    k_count  <<<3125, 256>>>(ei);
    k_scan1  <<<NBLK, 256>>>();
    k_scan2  <<<1, 256>>>();
    k_scan3  <<<NBLK, 256>>>();
    k_fill   <<<3125, 256>>>(ei);
    k_sortrow<<<NBLK, 256>>>();
    k_proj   <<<1563, dim3(96, 4)>>>(x, proj_w, proj_b, kq[0]);

    for (int k = 0; k < 8; k++) {
        double beta = log(0.5 / (double)(k + 1) + 1.0);
        int last = (k == 7);
        uint2 kqn = last ? make_uint2(0u, 0u) : kq[k + 1];
        float dlt  = (float)(1.0 / (double)(1u << (k + 1)));
        float invd = (float)(1u << (k + 1));
        k_layer<<<740, 256>>>(conv_ws + k * HID * HID, ke[k], kd[k], kqn,
                              (float)(1.0 - beta), (float)beta,
                              dlt, invd, last, k & 1);
    }
    k_out<<<392, 256>>>(out_w, out_b, out);
}

// round 10
// speedup vs baseline: 1.2224x; 1.1425x over previous
#include <cuda_runtime.h>
#include <stdint.h>
#include <math.h>

#define NN   50000
#define EE   800000
#define INC  128
#define HID  96
#define OUTC 40
#define NBLK 196   // ceil(NN/256)

// ---- device scratch (static, no allocations) ----
__device__ float  g_h0 [NN * HID];
__device__ float  g_hqA[NN * HID];
__device__ float  g_hqB[NN * HID];
__device__ int    g_cnt[NN];
__device__ int    g_cur[NN];
__device__ int    g_rowptr[NN + 1];
__device__ int    g_col[EE];
__device__ float2 g_cw[EE];
__device__ float  g_dis[NN];
__device__ int    g_bsum[NBLK];
__device__ int    g_boff[NBLK];
__device__ int    g_is64;

// ---- Threefry-2x32-20, JAX-exact ----
__device__ __forceinline__ void tf2x32(unsigned k0, unsigned k1,
                                       unsigned c0, unsigned c1,
                                       unsigned &o0, unsigned &o1)
{
    unsigned ks2 = k0 ^ k1 ^ 0x1BD11BDAu;
    unsigned x0 = c0 + k0, x1 = c1 + k1;
#define TFR(r) { x0 += x1; x1 = __funnelshift_l(x1, x1, r); x1 ^= x0; }
    TFR(13) TFR(15) TFR(26) TFR(6)
    x0 += k1;  x1 += ks2 + 1u;
    TFR(17) TFR(29) TFR(16) TFR(24)
    x0 += ks2; x1 += k0 + 2u;
    TFR(13) TFR(15) TFR(26) TFR(6)
    x0 += k0;  x1 += k1 + 3u;
    TFR(17) TFR(29) TFR(16) TFR(24)
    x0 += k1;  x1 += ks2 + 4u;
    TFR(13) TFR(15) TFR(26) TFR(6)
    x0 += ks2; x1 += k0 + 5u;
#undef TFR
    o0 = x0; o1 = x1;
}

__device__ __forceinline__ unsigned rbits(uint2 k, unsigned idx)
{
    unsigned a, b;
    tf2x32(k.x, k.y, 0u, idx, a, b);
    return a ^ b;
}

__device__ __forceinline__ float u01(unsigned bits)
{
    return __uint_as_float((bits >> 9) | 0x3f800000u) - 1.0f;
}

// XLA ErfInv32 (Giles); -log1p(-x*x) via MUFU-based __logf (safe: 1-x^2 >= ~1e-7)
__device__ __forceinline__ float erfinv_f(float x)
{
    float w = -__logf(fmaf(-x, x, 1.0f));
    float p;
    if (w < 5.0f) {
        w -= 2.5f;
        p = 2.81022636e-08f;
        p = fmaf(p, w, 3.43273939e-07f);
        p = fmaf(p, w, -3.5233877e-06f);
        p = fmaf(p, w, -4.39150654e-06f);
        p = fmaf(p, w, 0.00021858087f);
        p = fmaf(p, w, -0.00125372503f);
        p = fmaf(p, w, -0.00417768164f);
        p = fmaf(p, w, 0.246640727f);
        p = fmaf(p, w, 1.50140941f);
    } else {
        w = sqrtf(w) - 3.0f;
        p = -0.000200214257f;
        p = fmaf(p, w, 0.000100950558f);
        p = fmaf(p, w, 0.00134934322f);
        p = fmaf(p, w, -0.00367342844f);
        p = fmaf(p, w, 0.00573950773f);
        p = fmaf(p, w, -0.0076224613f);
        p = fmaf(p, w, 0.00943887047f);
        p = fmaf(p, w, 1.00167406f);
        p = fmaf(p, w, 2.83297682f);
    }
    return p * x;
}

// noise + relu + (dropout + next-layer dithered quantization)
__device__ __forceinline__ float epi(float z, unsigned idx,
                                     uint2 ke, uint2 kd, uint2 kqn,
                                     float dlt, float invd, int last)
{
    const float LO = -0.99999994f;
    float raw = u01(rbits(ke, idx));
    float u   = fmaxf(LO, fmaf(raw, 2.0f, LO));
    float g   = 1.4142135623730951f * erfinv_f(u);
    float h   = fmaxf(z + 0.01f * g, 0.0f);
    if (!last) {
        float ud = u01(rbits(kd, idx));
        h = (ud < 0.5f) ? (h + h) : 0.0f;
        float uq = u01(rbits(kqn, idx));
        float b  = (uq - 0.5f) * dlt;
        h = floorf((h + b) * invd) * dlt - b;
    }
    return h;
}

// ---- graph build ----
__global__ void k_zero()
{
    int i = blockIdx.x * blockDim.x + threadIdx.x;
    if (i < NN) { g_cnt[i] = 0; g_cur[i] = 0; }
}

__global__ void k_detect(const unsigned* __restrict__ w)
{
    if (threadIdx.x == 0) {
        int is64 = 1;
        for (int i = 0; i < 64; i++)
            if (w[2 * i + 1] != 0u) { is64 = 0; break; }
        g_is64 = is64;
    }
}

__global__ void k_count(const void* __restrict__ ei)
{
    int i = blockIdx.x * blockDim.x + threadIdx.x;
    if (i >= EE) return;
    int d = g_is64 ? (int)((const long long*)ei)[EE + i]
                   : ((const int*)ei)[EE + i];
    atomicAdd(&g_cnt[d], 1);
}

__global__ void k_scan1()
{
    __shared__ int ws[8];
    int tid = threadIdx.x, lane = tid & 31, warp = tid >> 5;
    int i = blockIdx.x * 256 + tid;
    int v = (i < NN) ? g_cnt[i] : 0;
    int s = v;
    #pragma unroll
    for (int o = 1; o < 32; o <<= 1) {
        int t = __shfl_up_sync(0xffffffffu, s, o);
        if (lane >= o) s += t;
    }
    if (lane == 31) ws[warp] = s;
    __syncthreads();
    if (warp == 0) {
        int w = (lane < 8) ? ws[lane] : 0;
        #pragma unroll
        for (int o = 1; o < 8; o <<= 1) {
            int t = __shfl_up_sync(0xffffffffu, w, o);
            if (lane >= o) w += t;
        }
        if (lane < 8) ws[lane] = w;
    }
    __syncthreads();
    s += (warp > 0) ? ws[warp - 1] : 0;
    if (i < NN) g_rowptr[i + 1] = s;
    if (tid == 255) g_bsum[blockIdx.x] = s;
}

__global__ void k_scan2()
{
    __shared__ int ws[8];
    int tid = threadIdx.x, lane = tid & 31, warp = tid >> 5;
    int v = (tid < NBLK) ? g_bsum[tid] : 0;
    int s = v;
    #pragma unroll
    for (int o = 1; o < 32; o <<= 1) {
        int t = __shfl_up_sync(0xffffffffu, s, o);
        if (lane >= o) s += t;
    }
    if (lane == 31) ws[warp] = s;
    __syncthreads();
    if (warp == 0) {
        int w = (lane < 8) ? ws[lane] : 0;
        #pragma unroll
        for (int o = 1; o < 8; o <<= 1) {
            int t = __shfl_up_sync(0xffffffffu, w, o);
            if (lane >= o) w += t;
        }
        if (lane < 8) ws[lane] = w;
    }
    __syncthreads();
    s += (warp > 0) ? ws[warp - 1] : 0;
    if (tid < NBLK) g_boff[tid] = s - v;
}

__global__ void k_scan3()
{
    int i = blockIdx.x * blockDim.x + threadIdx.x;
    if (i < NN) {
        g_rowptr[i + 1] += g_boff[i >> 8];
        if (i == 0) g_rowptr[0] = 0;
        g_dis[i] = (float)(1.0 / sqrt((double)(g_cnt[i] + 1)));
    }
}

__global__ void k_fill(const void* __restrict__ ei)
{
    int i = blockIdx.x * blockDim.x + threadIdx.x;
    if (i >= EE) return;
    int s, d;
    if (g_is64) {
        s = (int)((const long long*)ei)[i];
        d = (int)((const long long*)ei)[EE + i];
    } else {
        s = ((const int*)ei)[i];
        d = ((const int*)ei)[EE + i];
    }
    int pos = g_rowptr[d] + atomicAdd(&g_cur[d], 1);
    g_col[pos] = s;
}

__global__ void k_sortrow()
{
    int n = blockIdx.x * blockDim.x + threadIdx.x;
    if (n >= NN) return;
    int b = g_rowptr[n], e = g_rowptr[n + 1];
    for (int i = b + 1; i < e; i++) {
        int v = g_col[i], j = i - 1;
        while (j >= b && g_col[j] > v) { g_col[j + 1] = g_col[j]; j--; }
        g_col[j + 1] = v;
    }
    float dn = g_dis[n];
    for (int i = b; i < e; i++) {
        int s = g_col[i];
        g_cw[i] = make_float2(__int_as_float(s), g_dis[s] * dn);
    }
}

// ---- h0 = x @ Wp + b (smem-tiled, 4x6 register tile) + layer-0 quantization ----
#define PR  64
#define PKT 32
__global__ __launch_bounds__(256) void k_proj(const float* __restrict__ x,
                                              const float* __restrict__ Wp,
                                              const float* __restrict__ bp,
                                              uint2 kq0)
{
    __shared__ float sX[PR][PKT + 1];     // 8448 B (pad kills bank conflicts)
    __shared__ float sWt[PKT][HID];       // 12288 B
    int tid = threadIdx.x;
    int tx = tid & 15, ty = tid >> 4;     // tx: 6-col group, ty: 4-row group
    int r0 = blockIdx.x * PR;
    float acc[4][6];
    #pragma unroll
    for (int i = 0; i < 4; i++)
        #pragma unroll
        for (int j = 0; j < 6; j++) acc[i][j] = 0.0f;

    for (int k0 = 0; k0 < INC; k0 += PKT) {
        // x tile: 64 rows x 32 cols, float4 coalesced
        for (int i = tid; i < PR * PKT / 4; i += 256) {
            int rr = i >> 3, cc = (i & 7) << 2;
            int gr = r0 + rr; if (gr >= NN) gr = NN - 1;
            float4 v = *(const float4*)&x[(size_t)gr * INC + k0 + cc];
            sX[rr][cc] = v.x; sX[rr][cc+1] = v.y; sX[rr][cc+2] = v.z; sX[rr][cc+3] = v.w;
        }
        // w tile: 32 x 96
        for (int i = tid; i < PKT * HID / 4; i += 256) {
            int kk = i / 24, cc = (i % 24) << 2;
            *(float4*)&sWt[kk][cc] = *(const float4*)&Wp[(size_t)(k0 + kk) * HID + cc];
        }
        __syncthreads();
        #pragma unroll 8
        for (int kk = 0; kk < PKT; kk++) {
            float xs[4], ws[6];
            #pragma unroll
            for (int i = 0; i < 4; i++) xs[i] = sX[ty * 4 + i][kk];
            #pragma unroll
            for (int j = 0; j < 6; j++) ws[j] = sWt[kk][tx * 6 + j];
            #pragma unroll
            for (int i = 0; i < 4; i++)
                #pragma unroll
                for (int j = 0; j < 6; j++)
                    acc[i][j] = fmaf(xs[i], ws[j], acc[i][j]);
        }
        __syncthreads();
    }
    #pragma unroll
    for (int i = 0; i < 4; i++) {
        int rr = r0 + ty * 4 + i;
        if (rr < NN) {
            #pragma unroll
            for (int j = 0; j < 6; j++) {
                int c = tx * 6 + j;
                float h = acc[i][j] + bp[c];
                unsigned idx = (unsigned)(rr * HID + c);
                g_h0[idx] = h;
                float b = u01(rbits(kq0, idx)) - 0.5f;
                g_hqA[idx] = floorf(h + b) - b;   // delta = 1
            }
        }
    }
}

// ---- fused GCN2 layer: gather + residual + batched matmul + epilogue ----
#define WPB 8
#define NB  4     // nodes per warp batch (NN divisible by 4)
__global__ __launch_bounds__(256) void k_layer(const float* __restrict__ Wk,
                                               uint2 ke, uint2 kd, uint2 kqn,
                                               float omb, float betaf,
                                               float dlt, float invd,
                                               int last, int dir)
{
    __shared__ float sW[HID * HID];          // 36864 B
    __shared__ float sT[WPB][NB * HID];      // 12288 B  (total 49152 = static cap)
    const float* __restrict__ hin  = dir ? g_hqB : g_hqA;
    float* __restrict__       hout = dir ? g_hqA : g_hqB;
    for (int i = threadIdx.x * 4; i < HID * HID; i += 256 * 4)
        *(float4*)&sW[i] = *(const float4*)&Wk[i];
    __syncthreads();
    int warp = threadIdx.x >> 5, lane = threadIdx.x & 31;
    int f0 = lane, f1 = lane + 32, f2 = lane + 64;
    const int ngroups = NN / NB;             // 12500
    for (int g = blockIdx.x * WPB + warp; g < ngroups; g += gridDim.x * WPB) {
        int n0 = g * NB;
        // gather 4 nodes into sT
        if (lane < 24) {
            #pragma unroll
            for (int p = 0; p < NB; p++) {
                int n = n0 + p;
                float dn = g_dis[n];
                float ws = dn * dn;
                float4 v = ((const float4*)(hin + n * HID))[lane];
                float4 a = make_float4(v.x * ws, v.y * ws, v.z * ws, v.w * ws);
                int e  = g_rowptr[n];
                int e1 = g_rowptr[n + 1];
                for (; e + 2 <= e1; e += 2) {
                    float2 ca = g_cw[e];
                    float2 cb = g_cw[e + 1];
                    float4 ua = ((const float4*)(hin + __float_as_int(ca.x) * HID))[lane];
                    float4 ub = ((const float4*)(hin + __float_as_int(cb.x) * HID))[lane];
                    a.x = fmaf(ua.x, ca.y, a.x); a.y = fmaf(ua.y, ca.y, a.y);
                    a.z = fmaf(ua.z, ca.y, a.z); a.w = fmaf(ua.w, ca.y, a.w);
                    a.x = fmaf(ub.x, cb.y, a.x); a.y = fmaf(ub.y, cb.y, a.y);
                    a.z = fmaf(ub.z, cb.y, a.z); a.w = fmaf(ub.w, cb.y, a.w);
                }
                if (e < e1) {
                    float2 cw = g_cw[e];
                    float4 u = ((const float4*)(hin + __float_as_int(cw.x) * HID))[lane];
                    a.x = fmaf(u.x, cw.y, a.x); a.y = fmaf(u.y, cw.y, a.y);
                    a.z = fmaf(u.z, cw.y, a.z); a.w = fmaf(u.w, cw.y, a.w);
                }
                float4 h0v = ((const float4*)(g_h0 + n * HID))[lane];
                float4 t;
                t.x = 0.9f * a.x + 0.1f * h0v.x;
                t.y = 0.9f * a.y + 0.1f * h0v.y;
                t.z = 0.9f * a.z + 0.1f * h0v.z;
                t.w = 0.9f * a.w + 0.1f * h0v.w;
                ((float4*)&sT[warp][p * HID])[lane] = t;
            }
        }
        __syncwarp();
        // batched matmul: weights loaded once per j-pair, reused for 4 nodes
        float m[NB][3];
        #pragma unroll
        for (int p = 0; p < NB; p++) { m[p][0] = 0.f; m[p][1] = 0.f; m[p][2] = 0.f; }
        #pragma unroll 4
        for (int j = 0; j < HID; j += 2) {
            float wa0 = sW[j * HID + f0], wa1 = sW[j * HID + f1], wa2 = sW[j * HID + f2];
            float wb0 = sW[(j + 1) * HID + f0], wb1 = sW[(j + 1) * HID + f1], wb2 = sW[(j + 1) * HID + f2];
            #pragma unroll
            for (int p = 0; p < NB; p++) {
                float2 tv = *(const float2*)&sT[warp][p * HID + j];
                m[p][0] = fmaf(tv.x, wa0, m[p][0]); m[p][0] = fmaf(tv.y, wb0, m[p][0]);
                m[p][1] = fmaf(tv.x, wa1, m[p][1]); m[p][1] = fmaf(tv.y, wb1, m[p][1]);
                m[p][2] = fmaf(tv.x, wa2, m[p][2]); m[p][2] = fmaf(tv.y, wb2, m[p][2]);
            }
        }
        // epilogue: 12 independent RNG chains per lane
        #pragma unroll
        for (int p = 0; p < NB; p++) {
            unsigned base = (unsigned)((n0 + p) * HID);
            float t0 = sT[warp][p * HID + f0];
            float t1 = sT[warp][p * HID + f1];
            float t2 = sT[warp][p * HID + f2];
            hout[base + f0] = epi(omb * t0 + betaf * m[p][0], base + f0, ke, kd, kqn, dlt, invd, last);
            hout[base + f1] = epi(omb * t1 + betaf * m[p][1], base + f1, ke, kd, kqn, dlt, invd, last);
            hout[base + f2] = epi(omb * t2 + betaf * m[p][2], base + f2, ke, kd, kqn, dlt, invd, last);
        }
        __syncwarp();
    }
}

// ---- out = concat(h0, h) @ Wo + bo  (staged vectors, 2-node batching) ----
#define ONB 2
__global__ __launch_bounds__(256) void k_out(const float* __restrict__ Wo,
                                             const float* __restrict__ bo,
                                             float* __restrict__ out)
{
    __shared__ float sW[2 * HID * OUTC];        // 30720 B
    __shared__ float sV[WPB][ONB * 2 * HID];    // 12288 B
    __shared__ float sb[OUTC];
    for (int i = threadIdx.x; i < 2 * HID * OUTC; i += 256) sW[i] = Wo[i];
    for (int i = threadIdx.x; i < OUTC; i += 256) sb[i] = bo[i];
    __syncthreads();
    int warp = threadIdx.x >> 5, lane = threadIdx.x & 31;
    int lw = lane & 7;
    const int ngroups = NN / ONB;   // 25000
    for (int g = blockIdx.x * WPB + warp; g < ngroups; g += gridDim.x * WPB) {
        int n0 = g * ONB;
        if (lane < 24) {
            #pragma unroll
            for (int p = 0; p < ONB; p++) {
                int n = n0 + p;
                ((float4*)&sV[warp][p * 192])[lane]      = ((const float4*)(g_h0  + n * HID))[lane];
                ((float4*)&sV[warp][p * 192 + 96])[lane] = ((const float4*)(g_hqA + n * HID))[lane];
            }
        }
        __syncwarp();
        float a[ONB][2];
        #pragma unroll
        for (int p = 0; p < ONB; p++) { a[p][0] = 0.f; a[p][1] = 0.f; }
        #pragma unroll 4
        for (int j = 0; j < 192; j += 2) {
            float w0a = sW[j * OUTC + lane];
            float w1a = sW[j * OUTC + 32 + lw];
            float w0b = sW[(j + 1) * OUTC + lane];
            float w1b = sW[(j + 1) * OUTC + 32 + lw];
            #pragma unroll
            for (int p = 0; p < ONB; p++) {
                float2 tv = *(const float2*)&sV[warp][p * 192 + j];
                a[p][0] = fmaf(tv.x, w0a, a[p][0]); a[p][0] = fmaf(tv.y, w0b, a[p][0]);
                a[p][1] = fmaf(tv.x, w1a, a[p][1]); a[p][1] = fmaf(tv.y, w1b, a[p][1]);
            }
        }
        #pragma unroll
        for (int p = 0; p < ONB; p++) {
            int n = n0 + p;
            out[n * OUTC + lane] = a[p][0] + sb[lane];
            if (lane < 8) out[n * OUTC + 32 + lane] = a[p][1] + sb[32 + lane];
        }
        __syncwarp();
    }
}

// ---- host threefry for key derivation ----
static void host_tf(unsigned k0, unsigned k1, unsigned c0, unsigned c1,
                    unsigned &o0, unsigned &o1)
{
    unsigned ks2 = k0 ^ k1 ^ 0x1BD11BDAu;
    unsigned x0 = c0 + k0, x1 = c1 + k1;
#define HR(r) { x0 += x1; x1 = (x1 << r) | (x1 >> (32 - r)); x1 ^= x0; }
    HR(13) HR(15) HR(26) HR(6)
    x0 += k1;  x1 += ks2 + 1u;
    HR(17) HR(29) HR(16) HR(24)
    x0 += ks2; x1 += k0 + 2u;
    HR(13) HR(15) HR(26) HR(6)
    x0 += k0;  x1 += k1 + 3u;
    HR(17) HR(29) HR(16) HR(24)
    x0 += k1;  x1 += ks2 + 4u;
    HR(13) HR(15) HR(26) HR(6)
    x0 += ks2; x1 += k0 + 5u;
#undef HR
    o0 = x0; o1 = x1;
}

extern "C" void kernel_launch(void* const* d_in, const int* in_sizes, int n_in,
                              void* d_out, int out_size)
{
    const float* x       = (const float*)d_in[0];
    const void*  ei      = d_in[1];
    const float* proj_w  = (const float*)d_in[2];
    const float* proj_b  = (const float*)d_in[3];
    const float* conv_ws = (const float*)d_in[4];
    const float* out_w   = (const float*)d_in[5];
    const float* out_b   = (const float*)d_in[6];
    float* out = (float*)d_out;

    // split chain from jax.random.key(42): kq,ke,kd,key = split(key,4)
    uint2 kq[8], ke[8], kd[8];
    unsigned K0 = 0u, K1 = 42u;
    for (int k = 0; k < 8; k++) {
        unsigned a, b;
        host_tf(K0, K1, 0u, 0u, a, b); kq[k] = make_uint2(a, b);
        host_tf(K0, K1, 0u, 1u, a, b); ke[k] = make_uint2(a, b);
        host_tf(K0, K1, 0u, 2u, a, b); kd[k] = make_uint2(a, b);
        host_tf(K0, K1, 0u, 3u, a, b); K0 = a; K1 = b;
    }

    k_zero   <<<NBLK, 256>>>();
    k_detect <<<1, 32>>>((const unsigned*)ei);
    k_count  <<<3125, 256>>>(ei);
    k_scan1  <<<NBLK, 256>>>();
    k_scan2  <<<1, 256>>>();
    k_scan3  <<<NBLK, 256>>>();
    k_fill   <<<3125, 256>>>(ei);
    k_sortrow<<<NBLK, 256>>>();
    k_proj   <<<(NN + PR - 1) / PR, 256>>>(x, proj_w, proj_b, kq[0]);

    for (int k = 0; k < 8; k++) {
        double beta = log(0.5 / (double)(k + 1) + 1.0);
        int last = (k == 7);
        uint2 kqn = last ? make_uint2(0u, 0u) : kq[k + 1];
        float dlt  = (float)(1.0 / (double)(1u << (k + 1)));
        float invd = (float)(1u << (k + 1));
        k_layer<<<592, 256>>>(conv_ws + k * HID * HID, ke[k], kd[k], kqn,
                              (float)(1.0 - beta), (float)beta,
                              dlt, invd, last, k & 1);
    }
    k_out<<<592, 256>>>(out_w, out_b, out);
}